// round 14
// baseline (speedup 1.0000x reference)
#include <cuda_runtime.h>
#include <cuda_fp16.h>
#include <cstddef>

// InvertedResidualBlockME, fused 2-kernel plan:
//   K1: x = relu6(bn1(feats @ W1))         -> g_x fp16 [N,192]
//   K2: y = depthwise_sparse_gather(g_x)   9 x half2 row gathers, 4 pts/pass,
//       software-pipelined across the barriers; then
//       out = bn3(relu6(bn2(y)) @ W3) + feats   (packed fma.rn.f32x2 project)
// R13 profile: k_fuse smem-BYTES-bound (L1 78.7%). Fixes: W3 in 32 f32 regs
// (dup at use), int4 index loads (stride-12 snbr), [pp][tid] sp2 layout.

#define EPSF 1e-5f
#define MAXN 200000
#define HDIM 192
#define K1PTS 64   // points per block in K1 (two 32-point tiles)
#define K2PTS 64   // points per block in K2 (16 passes of 4)
#define NBS  12    // padded ints per point in snbr (int4-friendly)

__device__ __half g_x[(size_t)MAXN * HDIM];   // fp16 intermediate

// ---- packed f32x2 helpers ----
__device__ __forceinline__ unsigned long long pk2(float x, float y) {
    unsigned long long r;
    asm("mov.b64 %0, {%1, %2};" : "=l"(r) : "f"(x), "f"(y));
    return r;
}
__device__ __forceinline__ unsigned long long dup2(float x) {
    unsigned long long r;
    asm("mov.b64 %0, {%1, %1};" : "=l"(r) : "f"(x));
    return r;
}
__device__ __forceinline__ void unpk2(unsigned long long v, float& x, float& y) {
    asm("mov.b64 {%0, %1}, %2;" : "=f"(x), "=f"(y) : "l"(v));
}
__device__ __forceinline__ unsigned long long fma2(
    unsigned long long a, unsigned long long b, unsigned long long c) {
    unsigned long long d;
    asm("fma.rn.f32x2 %0, %1, %2, %3;" : "=l"(d) : "l"(a), "l"(b), "l"(c));
    return d;
}
__device__ __forceinline__ unsigned long long add2(
    unsigned long long a, unsigned long long b) {
    unsigned long long d;
    asm("add.rn.f32x2 %0, %1, %2;" : "=l"(d) : "l"(a), "l"(b));
    return d;
}
__device__ __forceinline__ float relu6f(float x) {
    return fminf(fmaxf(x, 0.f), 6.f);
}

// ---------------------------------------------------------------------------
// K1: expand GEMM + BN1 + relu6 -> fp16. 192 threads (one h-channel each),
// 64 points/block as two 32-point tiles (amortizes W1 column reg-fill).
// ---------------------------------------------------------------------------
__global__ __launch_bounds__(192, 3) void k_expand(
    const float* __restrict__ feats, const float* __restrict__ W1,
    const float* __restrict__ g1, const float* __restrict__ b1,
    const float* __restrict__ m1, const float* __restrict__ v1,
    int N)
{
    __shared__ __align__(16) float sft[2][32 * 32];

    const int tid = threadIdx.x;
    const int nb  = blockIdx.x * K1PTS;

    const int h = tid;
    unsigned long long w1p[32];               // duplicated (w,w) pairs
#pragma unroll
    for (int c = 0; c < 32; c++) { float w = W1[c * HDIM + h]; w1p[c] = pk2(w, w); }

    const float s1 = g1[h] * rsqrtf(v1[h] + EPSF);
    const float t1 = b1[h] - m1[h] * s1;

#pragma unroll
    for (int half = 0; half < 2; half++) {
        const int n0 = nb + 32 * half;
        if (n0 >= N) break;                   // uniform across block

        for (int i = tid; i < 1024; i += 192) {
            int m = i >> 5, c = i & 31;
            float f = (n0 + m < N) ? feats[(size_t)(n0 + m) * 32 + c] : 0.f;
            sft[half][c * 32 + (m ^ (c & 28))] = f;
        }
        __syncthreads();

        for (int q = 0; q < 8; q++) {         // quads of points
            const int m0 = 4 * q;
            if (n0 + m0 >= N) break;          // uniform across block
            unsigned long long a01 = pk2(0.f, 0.f), a23 = pk2(0.f, 0.f);
#pragma unroll
            for (int c = 0; c < 32; c++) {
                const ulonglong2 v = *reinterpret_cast<const ulonglong2*>(
                    &sft[half][c * 32 + (m0 ^ (c & 28))]);   // LDS.128 broadcast
                a01 = fma2(v.x, w1p[c], a01);
                a23 = fma2(v.y, w1p[c], a23);
            }
            float r[4];
            unpk2(a01, r[0], r[1]); unpk2(a23, r[2], r[3]);
#pragma unroll
            for (int j = 0; j < 4; j++) {
                if (n0 + m0 + j < N) {
                    float y = relu6f(fmaf(r[j], s1, t1));
                    g_x[(size_t)(n0 + m0 + j) * HDIM + h] = __float2half(y);
                }
            }
        }
    }
}

// ---------------------------------------------------------------------------
// K2: gather conv + BN2 + relu6 + project GEMM (f32x2) + BN3 + residual.
// 192 threads, 4 points/pass, gathers pipelined one pass ahead.
// W3: 32 f32 regs/thread (dup2 at use). snbr: stride-12, int4 loads.
// ---------------------------------------------------------------------------
__global__ __launch_bounds__(192, 3) void k_fuse(
    const int*   __restrict__ nbr,
    const float* __restrict__ W2, const float* __restrict__ W3,
    const float* __restrict__ g2, const float* __restrict__ b2,
    const float* __restrict__ m2, const float* __restrict__ v2,
    const float* __restrict__ g3, const float* __restrict__ b3,
    const float* __restrict__ m3, const float* __restrict__ v3,
    const float* __restrict__ feats, float* __restrict__ out,
    int N)
{
    __shared__ __align__(16) int snbr[K2PTS * NBS];
    __shared__ __align__(16) unsigned long long st2[HDIM * 2];  // [h][pp]
    __shared__ __align__(16) unsigned long long sp2[2 * HDIM];  // [pp][tid]

    const int tid = threadIdx.x;
    const int n0  = blockIdx.x * K2PTS;

    for (int i = tid; i < K2PTS * NBS; i += 192) {
        int p = i / NBS, k = i - p * NBS;
        snbr[i] = (k < 9 && n0 + p < N) ? __ldcs(&nbr[(size_t)(n0 + p) * 9 + k]) : -1;
    }

    // gather-role constants; BN2 scale folded into the depthwise weights
    const int gp = tid / 96;          // 0 -> points {0,1}, 1 -> points {2,3}
    const int cp = tid % 96;
    const float s2a = g2[2 * cp]     * rsqrtf(v2[2 * cp]     + EPSF);
    const float s2b = g2[2 * cp + 1] * rsqrtf(v2[2 * cp + 1] + EPSF);
    const float t2a = b2[2 * cp]     - m2[2 * cp]     * s2a;
    const float t2b = b2[2 * cp + 1] - m2[2 * cp + 1] * s2b;
    float2 w2p[9];
#pragma unroll
    for (int k = 0; k < 9; k++) {
        float2 wv = *reinterpret_cast<const float2*>(&W2[k * HDIM + 2 * cp]);
        w2p[k] = make_float2(wv.x * s2a, wv.y * s2b);
    }

    // project-role constants: W3 column slice in 32 f32 regs
    const int w = tid >> 5, l = tid & 31;
    float w3r[32];
#pragma unroll
    for (int i = 0; i < 32; i++) w3r[i] = W3[(size_t)(w * 32 + i) * 32 + l];

    // reduce-role constants (threads 0..63)
    float s3 = 0.f, t3 = 0.f;
    if (tid < 64) {
        int c = tid & 31;
        s3 = g3[c] * rsqrtf(v3[c] + EPSF);
        t3 = b3[c] - m3[c] * s3;
    }
    __syncthreads();   // covers snbr before first prefetch

    const __half2 h2z = __half2half2(__ushort_as_half(0));
    __half2 hA[9], hB[9];

    // index fetch helper pattern: 2x int4 + 1 scalar (broadcast LDS)
#define LOAD_IDX(ja, p_) do {                                              \
        const int4* v4_ = reinterpret_cast<const int4*>(&snbr[(p_) * NBS]);\
        int4 a0_ = v4_[0], a1_ = v4_[1];                                   \
        (ja)[0]=a0_.x; (ja)[1]=a0_.y; (ja)[2]=a0_.z; (ja)[3]=a0_.w;        \
        (ja)[4]=a1_.x; (ja)[5]=a1_.y; (ja)[6]=a1_.z; (ja)[7]=a1_.w;        \
        (ja)[8]=snbr[(p_) * NBS + 8];                                      \
    } while (0)

    // --- prologue: issue gathers for pass 0 ---
    {
        int jaA[9], jaB[9];
        LOAD_IDX(jaA, 2 * gp);
        LOAD_IDX(jaB, 2 * gp + 1);
#pragma unroll
        for (int k = 0; k < 9; k++) {
            hA[k] = (jaA[k] >= 0) ? *reinterpret_cast<const __half2*>(
                        &g_x[(size_t)jaA[k] * HDIM + 2 * cp]) : h2z;
            hB[k] = (jaB[k] >= 0) ? *reinterpret_cast<const __half2*>(
                        &g_x[(size_t)jaB[k] * HDIM + 2 * cp]) : h2z;
        }
    }

    const int npass = K2PTS / 4;
    for (int q = 0; q < npass; q++) {
        const int n = n0 + 4 * q;
        if (n >= N) break;                     // uniform across block

        // --- consume prefetched gathers: depthwise accumulate (+folded BN2) ---
        float aA0 = 0.f, aA1 = 0.f, aB0 = 0.f, aB1 = 0.f;
#pragma unroll
        for (int k = 0; k < 9; k++) {
            float2 vA = __half22float2(hA[k]);
            float2 vB = __half22float2(hB[k]);
            aA0 = fmaf(vA.x, w2p[k].x, aA0);
            aA1 = fmaf(vA.y, w2p[k].y, aA1);
            aB0 = fmaf(vB.x, w2p[k].x, aB0);
            aB1 = fmaf(vB.y, w2p[k].y, aB1);
        }
        st2[(2 * cp)     * 2 + gp] = pk2(relu6f(aA0 + t2a), relu6f(aB0 + t2a));
        st2[(2 * cp + 1) * 2 + gp] = pk2(relu6f(aA1 + t2b), relu6f(aB1 + t2b));

        // --- issue next pass's gathers BEFORE the barrier (fly over proj) ---
        if (q + 1 < npass && n0 + 4 * (q + 1) < N) {
            int jaA[9], jaB[9];
            LOAD_IDX(jaA, 4 * (q + 1) + 2 * gp);
            LOAD_IDX(jaB, 4 * (q + 1) + 2 * gp + 1);
#pragma unroll
            for (int k = 0; k < 9; k++) {
                hA[k] = (jaA[k] >= 0) ? *reinterpret_cast<const __half2*>(
                            &g_x[(size_t)jaA[k] * HDIM + 2 * cp]) : h2z;
                hB[k] = (jaB[k] >= 0) ? *reinterpret_cast<const __half2*>(
                            &g_x[(size_t)jaB[k] * HDIM + 2 * cp]) : h2z;
            }
        }
        __syncthreads();

        // --- project partials: 32 st2 broadcasts + reg w3 (dup at use) ---
        unsigned long long acc0 = pk2(0.f, 0.f), acc1 = pk2(0.f, 0.f);
#pragma unroll
        for (int i = 0; i < 32; i++) {
            const ulonglong2 tv = *reinterpret_cast<const ulonglong2*>(
                &st2[(w * 32 + i) * 2]);          // LDS.128 broadcast
            const unsigned long long wv = dup2(w3r[i]);
            acc0 = fma2(tv.x, wv, acc0);
            acc1 = fma2(tv.y, wv, acc1);
        }
        sp2[0 * HDIM + tid] = acc0;               // pp=0 partials
        sp2[1 * HDIM + tid] = acc1;               // pp=1 partials
        __syncthreads();

        // --- reduce 6 warps, packed adds; pp = tid>>5 (points 2pp,2pp+1) ---
        if (tid < 64) {
            const int pp = tid >> 5, c = tid & 31;
            const unsigned long long* row = &sp2[pp * HDIM];
            unsigned long long s = row[0 * 32 + c];
            s = add2(s, row[1 * 32 + c]);
            s = add2(s, row[2 * 32 + c]);
            s = add2(s, row[3 * 32 + c]);
            s = add2(s, row[4 * 32 + c]);
            s = add2(s, row[5 * 32 + c]);
            float sx, sy; unpk2(s, sx, sy);
            const int np0 = n + 2 * pp, np1 = n + 2 * pp + 1;
            if (np0 < N)
                __stcs(&out[(size_t)np0 * 32 + c],
                       fmaf(sx, s3, t3) + feats[(size_t)np0 * 32 + c]);
            if (np1 < N)
                __stcs(&out[(size_t)np1 * 32 + c],
                       fmaf(sy, s3, t3) + feats[(size_t)np1 * 32 + c]);
        }
        // st2 of pass q+1 written only after sync2(q) ordered this pass's
        // project reads; sp2 of q+1 only after sync1(q+1), which the reduce
        // threads gate. Prefetch touches only registers. Safe.
    }
#undef LOAD_IDX
}

// ---------------------------------------------------------------------------
extern "C" void kernel_launch(void* const* d_in, const int* in_sizes, int n_in,
                              void* d_out, int out_size)
{
    const float* feats = (const float*)d_in[0];
    const int*   nbr   = (const int*)  d_in[1];
    const float* W1    = (const float*)d_in[2];
    const float* W2    = (const float*)d_in[3];
    const float* W3    = (const float*)d_in[4];
    const float* g1 = (const float*)d_in[5],  *b1 = (const float*)d_in[6];
    const float* m1 = (const float*)d_in[7],  *v1 = (const float*)d_in[8];
    const float* g2 = (const float*)d_in[9],  *b2 = (const float*)d_in[10];
    const float* m2 = (const float*)d_in[11], *v2 = (const float*)d_in[12];
    const float* g3 = (const float*)d_in[13], *b3 = (const float*)d_in[14];
    const float* m3 = (const float*)d_in[15], *v3 = (const float*)d_in[16];
    float* out = (float*)d_out;

    int N = in_sizes[0] / 32;
    if (N > MAXN) N = MAXN;

    k_expand<<<(N + K1PTS - 1) / K1PTS, 192>>>(feats, W1, g1, b1, m1, v1, N);
    k_fuse<<<(N + K2PTS - 1) / K2PTS, 192>>>(nbr, W2, W3,
                                             g2, b2, m2, v2,
                                             g3, b3, m3, v3,
                                             feats, out, N);
}

// round 16
// speedup vs baseline: 1.0775x; 1.0775x over previous
#include <cuda_runtime.h>
#include <cuda_fp16.h>
#include <cstddef>

// InvertedResidualBlockME, fused 2-kernel plan:
//   K1: x = relu6(bn1(feats @ W1))         -> g_x fp16 [N,192]
//   K2: y = depthwise_sparse_gather(g_x)   9 x half2 row gathers, 4 pts/pass,
//       software-pipelined across the barriers; then
//       out = bn3(relu6(bn2(y)) @ W3) + feats   (packed fma.rn.f32x2 project)
// R13/R14 lesson: occupancy (35%) must be held; cut smem wavefronts only in
// register-neutral ways. W3 stays in smem (transposed, LDS.128); index loads
// via int4; gather staging stP[pp][h] written with STS.128; sp2 [pp][tid].

#define EPSF 1e-5f
#define MAXN 200000
#define HDIM 192
#define K1PTS 64   // points per block in K1 (two 32-point tiles)
#define K2PTS 64   // points per block in K2 (16 passes of 4)
#define NBS  12    // padded ints per point in snbr (int4-friendly)
#define W3PITCH 196  // floats per lane-row of transposed W3 (196%32=4 -> conflict-free)

__device__ __half g_x[(size_t)MAXN * HDIM];   // fp16 intermediate

// ---- packed f32x2 helpers ----
__device__ __forceinline__ unsigned long long pk2(float x, float y) {
    unsigned long long r;
    asm("mov.b64 %0, {%1, %2};" : "=l"(r) : "f"(x), "f"(y));
    return r;
}
__device__ __forceinline__ unsigned long long dup2(float x) {
    unsigned long long r;
    asm("mov.b64 %0, {%1, %1};" : "=l"(r) : "f"(x));
    return r;
}
__device__ __forceinline__ void unpk2(unsigned long long v, float& x, float& y) {
    asm("mov.b64 {%0, %1}, %2;" : "=f"(x), "=f"(y) : "l"(v));
}
__device__ __forceinline__ unsigned long long fma2(
    unsigned long long a, unsigned long long b, unsigned long long c) {
    unsigned long long d;
    asm("fma.rn.f32x2 %0, %1, %2, %3;" : "=l"(d) : "l"(a), "l"(b), "l"(c));
    return d;
}
__device__ __forceinline__ unsigned long long add2(
    unsigned long long a, unsigned long long b) {
    unsigned long long d;
    asm("add.rn.f32x2 %0, %1, %2;" : "=l"(d) : "l"(a), "l"(b));
    return d;
}
__device__ __forceinline__ float relu6f(float x) {
    return fminf(fmaxf(x, 0.f), 6.f);
}

// ---------------------------------------------------------------------------
// K1: expand GEMM + BN1 + relu6 -> fp16. 192 threads (one h-channel each),
// 64 points/block as two 32-point tiles (amortizes W1 column reg-fill).
// ---------------------------------------------------------------------------
__global__ __launch_bounds__(192, 3) void k_expand(
    const float* __restrict__ feats, const float* __restrict__ W1,
    const float* __restrict__ g1, const float* __restrict__ b1,
    const float* __restrict__ m1, const float* __restrict__ v1,
    int N)
{
    __shared__ __align__(16) float sft[2][32 * 32];

    const int tid = threadIdx.x;
    const int nb  = blockIdx.x * K1PTS;

    const int h = tid;
    unsigned long long w1p[32];               // duplicated (w,w) pairs
#pragma unroll
    for (int c = 0; c < 32; c++) { float w = W1[c * HDIM + h]; w1p[c] = pk2(w, w); }

    const float s1 = g1[h] * rsqrtf(v1[h] + EPSF);
    const float t1 = b1[h] - m1[h] * s1;

#pragma unroll
    for (int half = 0; half < 2; half++) {
        const int n0 = nb + 32 * half;
        if (n0 >= N) break;                   // uniform across block

        for (int i = tid; i < 1024; i += 192) {
            int m = i >> 5, c = i & 31;
            float f = (n0 + m < N) ? feats[(size_t)(n0 + m) * 32 + c] : 0.f;
            sft[half][c * 32 + (m ^ (c & 28))] = f;
        }
        __syncthreads();

        for (int q = 0; q < 8; q++) {         // quads of points
            const int m0 = 4 * q;
            if (n0 + m0 >= N) break;          // uniform across block
            unsigned long long a01 = pk2(0.f, 0.f), a23 = pk2(0.f, 0.f);
#pragma unroll
            for (int c = 0; c < 32; c++) {
                const ulonglong2 v = *reinterpret_cast<const ulonglong2*>(
                    &sft[half][c * 32 + (m0 ^ (c & 28))]);   // LDS.128 broadcast
                a01 = fma2(v.x, w1p[c], a01);
                a23 = fma2(v.y, w1p[c], a23);
            }
            float r[4];
            unpk2(a01, r[0], r[1]); unpk2(a23, r[2], r[3]);
#pragma unroll
            for (int j = 0; j < 4; j++) {
                if (n0 + m0 + j < N) {
                    float y = relu6f(fmaf(r[j], s1, t1));
                    g_x[(size_t)(n0 + m0 + j) * HDIM + h] = __float2half(y);
                }
            }
        }
    }
}

// ---------------------------------------------------------------------------
// K2: gather conv + BN2 + relu6 + project GEMM (f32x2) + BN3 + residual.
// 192 threads, 4 points/pass, gathers pipelined one pass ahead.
// ---------------------------------------------------------------------------
__global__ __launch_bounds__(192, 4) void k_fuse(
    const int*   __restrict__ nbr,
    const float* __restrict__ W2, const float* __restrict__ W3,
    const float* __restrict__ g2, const float* __restrict__ b2,
    const float* __restrict__ m2, const float* __restrict__ v2,
    const float* __restrict__ g3, const float* __restrict__ b3,
    const float* __restrict__ m3, const float* __restrict__ v3,
    const float* __restrict__ feats, float* __restrict__ out,
    int N)
{
    __shared__ __align__(16) int snbr[K2PTS * NBS];
    __shared__ __align__(16) unsigned long long stP[2][HDIM];  // [pp][h]
    __shared__ __align__(16) unsigned long long sp2[2][HDIM];  // [pp][tid]
    __shared__ __align__(16) float w3t[32 * W3PITCH];          // transposed W3 [l][h]

    const int tid = threadIdx.x;
    const int n0  = blockIdx.x * K2PTS;

    for (int i = tid; i < K2PTS * NBS; i += 192) {
        int p = i / NBS, k = i - p * NBS;
        snbr[i] = (k < 9 && n0 + p < N) ? __ldcs(&nbr[(size_t)(n0 + p) * 9 + k]) : -1;
    }
    // stage W3 transposed: w3t[l][h] = W3[h][l]
    for (int i = tid; i < HDIM * 32; i += 192) {
        int hh = i >> 5, ll = i & 31;
        w3t[ll * W3PITCH + hh] = W3[i];
    }

    // gather-role constants; BN2 scale folded into the depthwise weights
    const int gp = tid / 96;          // 0 -> points {0,1}, 1 -> points {2,3}
    const int cp = tid % 96;
    const float s2a = g2[2 * cp]     * rsqrtf(v2[2 * cp]     + EPSF);
    const float s2b = g2[2 * cp + 1] * rsqrtf(v2[2 * cp + 1] + EPSF);
    const float t2a = b2[2 * cp]     - m2[2 * cp]     * s2a;
    const float t2b = b2[2 * cp + 1] - m2[2 * cp + 1] * s2b;
    float2 w2p[9];
#pragma unroll
    for (int k = 0; k < 9; k++) {
        float2 wv = *reinterpret_cast<const float2*>(&W2[k * HDIM + 2 * cp]);
        w2p[k] = make_float2(wv.x * s2a, wv.y * s2b);
    }

    // project-role constants: w3t row l, cols 32w..32w+31
    const int w = tid >> 5, l = tid & 31;
    const float* w3row = &w3t[l * W3PITCH + w * 32];

    // reduce-role constants (threads 0..63)
    float s3 = 0.f, t3 = 0.f;
    if (tid < 64) {
        int c = tid & 31;
        s3 = g3[c] * rsqrtf(v3[c] + EPSF);
        t3 = b3[c] - m3[c] * s3;
    }
    __syncthreads();   // covers snbr + w3t before first use

    const __half2 h2z = __half2half2(__ushort_as_half(0));
    __half2 hA[9], hB[9];

    // index fetch: 2x int4 + 1 scalar (all broadcast LDS; p_ uniform per warp)
#define LOAD_IDX(ja, p_) do {                                              \
        const int4* v4_ = reinterpret_cast<const int4*>(&snbr[(p_) * NBS]);\
        int4 a0_ = v4_[0], a1_ = v4_[1];                                   \
        (ja)[0]=a0_.x; (ja)[1]=a0_.y; (ja)[2]=a0_.z; (ja)[3]=a0_.w;        \
        (ja)[4]=a1_.x; (ja)[5]=a1_.y; (ja)[6]=a1_.z; (ja)[7]=a1_.w;        \
        (ja)[8]=snbr[(p_) * NBS + 8];                                      \
    } while (0)

    // --- prologue: issue gathers for pass 0 ---
    {
        int jaA[9], jaB[9];
        LOAD_IDX(jaA, 2 * gp);
        LOAD_IDX(jaB, 2 * gp + 1);
#pragma unroll
        for (int k = 0; k < 9; k++) {
            hA[k] = (jaA[k] >= 0) ? *reinterpret_cast<const __half2*>(
                        &g_x[(size_t)jaA[k] * HDIM + 2 * cp]) : h2z;
            hB[k] = (jaB[k] >= 0) ? *reinterpret_cast<const __half2*>(
                        &g_x[(size_t)jaB[k] * HDIM + 2 * cp]) : h2z;
        }
    }

    const int npass = K2PTS / 4;
    for (int q = 0; q < npass; q++) {
        const int n = n0 + 4 * q;
        if (n >= N) break;                     // uniform across block

        // --- consume prefetched gathers: depthwise accumulate (+folded BN2) ---
        float aA0 = 0.f, aA1 = 0.f, aB0 = 0.f, aB1 = 0.f;
#pragma unroll
        for (int k = 0; k < 9; k++) {
            float2 vA = __half22float2(hA[k]);
            float2 vB = __half22float2(hB[k]);
            aA0 = fmaf(vA.x, w2p[k].x, aA0);
            aA1 = fmaf(vA.y, w2p[k].y, aA1);
            aB0 = fmaf(vB.x, w2p[k].x, aB0);
            aB1 = fmaf(vB.y, w2p[k].y, aB1);
        }
        // stP[gp][h] = (t_{h,point 2gp}, t_{h,point 2gp+1}); one STS.128
        {
            ulonglong2 sv;
            sv.x = pk2(relu6f(aA0 + t2a), relu6f(aB0 + t2a));  // channel 2cp
            sv.y = pk2(relu6f(aA1 + t2b), relu6f(aB1 + t2b));  // channel 2cp+1
            *reinterpret_cast<ulonglong2*>(&stP[gp][2 * cp]) = sv;
        }

        // --- issue next pass's gathers BEFORE the barrier (fly over proj) ---
        if (q + 1 < npass && n0 + 4 * (q + 1) < N) {
            int jaA[9], jaB[9];
            LOAD_IDX(jaA, 4 * (q + 1) + 2 * gp);
            LOAD_IDX(jaB, 4 * (q + 1) + 2 * gp + 1);
#pragma unroll
            for (int k = 0; k < 9; k++) {
                hA[k] = (jaA[k] >= 0) ? *reinterpret_cast<const __half2*>(
                            &g_x[(size_t)jaA[k] * HDIM + 2 * cp]) : h2z;
                hB[k] = (jaB[k] >= 0) ? *reinterpret_cast<const __half2*>(
                            &g_x[(size_t)jaB[k] * HDIM + 2 * cp]) : h2z;
            }
        }
        __syncthreads();

        // --- project: per 4 channels: 1 LDS.128 w3 + 4 broadcast ulonglong2 ---
        unsigned long long acc0 = pk2(0.f, 0.f), acc1 = pk2(0.f, 0.f);
#pragma unroll
        for (int i4 = 0; i4 < 8; i4++) {
            const float4 wv = *reinterpret_cast<const float4*>(&w3row[i4 * 4]);
            const int c0 = w * 32 + i4 * 4;
            const ulonglong2 a01 = *reinterpret_cast<const ulonglong2*>(&stP[0][c0]);
            const ulonglong2 a23 = *reinterpret_cast<const ulonglong2*>(&stP[0][c0 + 2]);
            const ulonglong2 b01 = *reinterpret_cast<const ulonglong2*>(&stP[1][c0]);
            const ulonglong2 b23 = *reinterpret_cast<const ulonglong2*>(&stP[1][c0 + 2]);
            const unsigned long long wx = dup2(wv.x), wy = dup2(wv.y);
            const unsigned long long wz = dup2(wv.z), ww = dup2(wv.w);
            acc0 = fma2(a01.x, wx, acc0);  acc1 = fma2(b01.x, wx, acc1);
            acc0 = fma2(a01.y, wy, acc0);  acc1 = fma2(b01.y, wy, acc1);
            acc0 = fma2(a23.x, wz, acc0);  acc1 = fma2(b23.x, wz, acc1);
            acc0 = fma2(a23.y, ww, acc0);  acc1 = fma2(b23.y, ww, acc1);
        }
        sp2[0][tid] = acc0;                   // partials for points (0,1)
        sp2[1][tid] = acc1;                   // partials for points (2,3)
        __syncthreads();

        // --- reduce 6 warps, packed adds; pp = tid>>5 (points 2pp,2pp+1) ---
        if (tid < 64) {
            const int pp = tid >> 5, c = tid & 31;
            const unsigned long long* row = sp2[pp];
            unsigned long long s = row[0 * 32 + c];
            s = add2(s, row[1 * 32 + c]);
            s = add2(s, row[2 * 32 + c]);
            s = add2(s, row[3 * 32 + c]);
            s = add2(s, row[4 * 32 + c]);
            s = add2(s, row[5 * 32 + c]);
            float sx, sy; unpk2(s, sx, sy);
            const int np0 = n + 2 * pp, np1 = n + 2 * pp + 1;
            if (np0 < N)
                __stcs(&out[(size_t)np0 * 32 + c],
                       fmaf(sx, s3, t3) + feats[(size_t)np0 * 32 + c]);
            if (np1 < N)
                __stcs(&out[(size_t)np1 * 32 + c],
                       fmaf(sy, s3, t3) + feats[(size_t)np1 * 32 + c]);
        }
        // stP of pass q+1 written only after sync2(q) (orders project reads);
        // sp2 of pass q+1 only after sync1(q+1), which reduce threads gate.
    }
#undef LOAD_IDX
}

// ---------------------------------------------------------------------------
extern "C" void kernel_launch(void* const* d_in, const int* in_sizes, int n_in,
                              void* d_out, int out_size)
{
    const float* feats = (const float*)d_in[0];
    const int*   nbr   = (const int*)  d_in[1];
    const float* W1    = (const float*)d_in[2];
    const float* W2    = (const float*)d_in[3];
    const float* W3    = (const float*)d_in[4];
    const float* g1 = (const float*)d_in[5],  *b1 = (const float*)d_in[6];
    const float* m1 = (const float*)d_in[7],  *v1 = (const float*)d_in[8];
    const float* g2 = (const float*)d_in[9],  *b2 = (const float*)d_in[10];
    const float* m2 = (const float*)d_in[11], *v2 = (const float*)d_in[12];
    const float* g3 = (const float*)d_in[13], *b3 = (const float*)d_in[14];
    const float* m3 = (const float*)d_in[15], *v3 = (const float*)d_in[16];
    float* out = (float*)d_out;

    int N = in_sizes[0] / 32;
    if (N > MAXN) N = MAXN;

    k_expand<<<(N + K1PTS - 1) / K1PTS, 192>>>(feats, W1, g1, b1, m1, v1, N);
    k_fuse<<<(N + K2PTS - 1) / K2PTS, 192>>>(nbr, W2, W3,
                                             g2, b2, m2, v2,
                                             g3, b3, m3, v3,
                                             feats, out, N);
}